// round 5
// baseline (speedup 1.0000x reference)
#include <cuda_runtime.h>

// HausdorffDistanceLoss_8624294331223 — FINAL (converged)
//
// Reference math collapses to the constant 0.0f, bit-exactly:
//   b = (mask > 0.5) is a 0/1 mask; conv3x3_ones(b) sums <=9 ones — exact
//   small integers in fp32, and conv is linear, so
//     eroded = -conv3x3(-b) == conv3x3(b) == dilated   (bit-exact)
//   => boundary = ((dilated - eroded) > 0) == (0 > 0) == all zeros
//   => both boundary coordinate sets empty (valid masks all-false)
//   => directed distances = sum(0)/max(0,1) = 0 in both directions
//   => nonempty = False => where() selects 0.0f — for EVERY input.
//
// Optimization history (all rel_err = 0.0):
//   R1 kernel node (1-store kernel):  4.58 us   (CTA launch machinery)
//   R2 memset node (4 bytes):         3.20 us   <- WINNER (front-end path)
//   R3 D2D memcpy node (4 bytes):     4.86 us   (copy-engine dispatch)
//   R4 re-bench of memset node:       3.26 us   (confirms floor, noise-level)
//
// Structural floor argument: the captured graph must contain >=1 node, and
// d_out is poisoned to 0xAA before timing, so at least one 4-byte write is
// mandatory. Of the three capture-legal node types that can perform it, the
// memset node is measured cheapest; its residual ~3.2 us is fixed graph-replay
// + front-end service overhead outside kernel_launch's control.
//
// fp32 0.0f == all-zero bytes => cudaMemsetAsync(d_out, 0, 4*out_size) is
// bit-exact, graph-capturable, allocation-free, and deterministic.

extern "C" void kernel_launch(void* const* d_in, const int* in_sizes, int n_in,
                              void* d_out, int out_size) {
    (void)d_in; (void)in_sizes; (void)n_in;
    cudaMemsetAsync(d_out, 0, (size_t)out_size * sizeof(float), 0);
}